// round 4
// baseline (speedup 1.0000x reference)
#include <cuda_runtime.h>
#include <cuda_bf16.h>

// Inputs (metadata order):
//  0: x        float32 [N]
//  1: y        float32 [N]
//  2: values   float32 [N]
//  3: lookup_table int32 [Q*R]   (not read: index computed analytically)
//  4: hex_size       float32 [1]
//  5: rotation_angle float32 [1]
//  6: hex_offset_x   float32 [1]
//  7: hex_offset_y   float32 [1]
//  8: q_min          int32   [1]   (== -R for this hex layout)
//  9: r_min          int32   [1]
// 10: n_pixels      int32   [1]
// out: float32 [n_pixels]

#define NPIX_MAX 2048
#define THREADS  512
#define BLOCKS   592   // 148 SMs * 4 resident blocks -> single wave

__global__ void zero_out_kernel(float* __restrict__ out, int n) {
    int i = blockIdx.x * blockDim.x + threadIdx.x;
    if (i < n) out[i] = 0.0f;
}

// GLOBAL_PATH=0 -> shared-memory histogram, =1 -> L2 RED atomics
template <int GLOBAL_PATH>
__device__ __forceinline__ void process_one(
    float xv, float yv, float val,
    float Aq, float Bq, float Cq,
    float Ar, float Br, float Cr,
    int R, float* __restrict__ sh, float* __restrict__ gout)
{
    float q = fmaf(Aq, xv, fmaf(Bq, yv, Cq));
    float r = fmaf(Ar, xv, fmaf(Br, yv, Cr));
    // axial round (round-half-even == jnp.round)
    float s  = -q - r;
    float qr = rintf(q);
    float rr = rintf(r);
    float sr = rintf(s);
    float qd = fabsf(qr - q);
    float rd = fabsf(rr - r);
    float sd = fabsf(sr - s);
    if (qd > rd && qd > sd) qr = -rr - sr;
    if (rd > qd && rd > sd) rr = -qr - sr;   // uses updated qr, like reference

    int a = (int)qr;           // axial q
    int b = (int)rr;           // axial r
    // hex membership + analytic pixel index (q-major enumeration, r ascending)
    int amin = min(a, 0);
    int amax = max(a, 0);
    int rlo  = -R - amin;      // max(-R, -a-R)
    int rhi  =  R - amax;      // min(R, -a+R)
    bool valid = (a >= -R) & (a <= R) & (b >= rlo) & (b <= rhi);
    if (valid) {
        int u = amin + R;
        int e = amax;
        int off = u * (R + 1) + ((u * (u - 1)) >> 1)
                + e * (2 * R + 1) - ((e * (e - 1)) >> 1);
        int pix = off + (b - rlo);
        if (GLOBAL_PATH) {
            atomicAdd(&gout[pix], val);   // RED to L2 atomic ALUs
        } else {
            atomicAdd(&sh[pix], val);     // per-SM shared atomic unit
        }
    }
}

__global__ __launch_bounds__(THREADS, 4)
void hex_hist_kernel(
    const float* __restrict__ x,
    const float* __restrict__ y,
    const float* __restrict__ vals,
    const float* __restrict__ hs_p,
    const float* __restrict__ rot_p,
    const float* __restrict__ ox_p,
    const float* __restrict__ oy_p,
    const int*   __restrict__ qmin_p,
    float* __restrict__ out,
    int n, int n_pix)
{
    __shared__ float sh[NPIX_MAX];
    for (int i = threadIdx.x; i < n_pix; i += THREADS) sh[i] = 0.0f;
    __syncthreads();

    // fold rotation + offsets + hex scale into 2 affine maps:
    //   q = Aq*x + Bq*y + Cq     r = Ar*x + Br*y + Cr
    const float hs  = *hs_p;
    const float rot = *rot_p;
    const float ca  = cosf(-rot);
    const float sa  = sinf(-rot);
    const float ox  = *ox_p;
    const float oy  = *oy_p;
    const int   R   = -(*qmin_p);

    const float inv_hs = 1.0f / hs;
    const float c1 = 0.57735026918962576f;  // sqrt(3)/3
    const float c2 = 1.0f / 3.0f;
    const float c3 = 2.0f / 3.0f;
    const float Aq = inv_hs * (c1 * ca - c2 * sa);
    const float Bq = inv_hs * (-c1 * sa - c2 * ca);
    const float Cq = -(Aq * ox + Bq * oy);
    const float Ar = inv_hs * c3 * sa;
    const float Br = inv_hs * c3 * ca;
    const float Cr = -(Ar * ox + Br * oy);

    int tid    = blockIdx.x * THREADS + threadIdx.x;
    int stride = gridDim.x * THREADS;

    int n4 = n >> 2;
    const float4* __restrict__ x4 = (const float4*)x;
    const float4* __restrict__ y4 = (const float4*)y;
    const float4* __restrict__ v4 = (const float4*)vals;
    for (int i = tid; i < n4; i += stride) {
        float4 xa = x4[i];
        float4 ya = y4[i];
        float4 va = v4[i];
        // split the atomic stream across the two independent atomic engines:
        // 2 photons -> per-SM shared unit, 2 photons -> L2 LTS atomic ALUs
        process_one<0>(xa.x, ya.x, va.x, Aq, Bq, Cq, Ar, Br, Cr, R, sh, out);
        process_one<1>(xa.y, ya.y, va.y, Aq, Bq, Cq, Ar, Br, Cr, R, sh, out);
        process_one<0>(xa.z, ya.z, va.z, Aq, Bq, Cq, Ar, Br, Cr, R, sh, out);
        process_one<1>(xa.w, ya.w, va.w, Aq, Bq, Cq, Ar, Br, Cr, R, sh, out);
    }
    // tail (n not multiple of 4)
    for (int i = (n4 << 2) + tid; i < n; i += stride) {
        process_one<0>(x[i], y[i], vals[i], Aq, Bq, Cq, Ar, Br, Cr, R, sh, out);
    }

    __syncthreads();
    for (int i = threadIdx.x; i < n_pix; i += THREADS) {
        float v = sh[i];
        if (v != 0.0f) atomicAdd(&out[i], v);
    }
}

extern "C" void kernel_launch(void* const* d_in, const int* in_sizes, int n_in,
                              void* d_out, int out_size) {
    const float* x      = (const float*)d_in[0];
    const float* y      = (const float*)d_in[1];
    const float* vals   = (const float*)d_in[2];
    const float* hs_p   = (const float*)d_in[4];
    const float* rot_p  = (const float*)d_in[5];
    const float* ox_p   = (const float*)d_in[6];
    const float* oy_p   = (const float*)d_in[7];
    const int*   qmin_p = (const int*)d_in[8];
    float* out = (float*)d_out;

    int n = in_sizes[0];
    int n_pix = out_size;

    zero_out_kernel<<<(out_size + 255) / 256, 256>>>(out, out_size);

    hex_hist_kernel<<<BLOCKS, THREADS>>>(
        x, y, vals, hs_p, rot_p, ox_p, oy_p, qmin_p,
        out, n, n_pix);
}

// round 5
// speedup vs baseline: 11.1043x; 11.1043x over previous
#include <cuda_runtime.h>
#include <cuda_bf16.h>

// Inputs (metadata order):
//  0: x        float32 [N]
//  1: y        float32 [N]
//  2: values   float32 [N]
//  3: lookup_table int32 [Q*R]   (not read: index computed analytically)
//  4: hex_size       float32 [1]
//  5: rotation_angle float32 [1]
//  6: hex_offset_x   float32 [1]
//  7: hex_offset_y   float32 [1]
//  8: q_min          int32   [1]   (== -R for this hex layout)
//  9: r_min          int32   [1]
// 10: n_pixels      int32   [1]
// out: float32 [n_pixels]

#define NPIX_STRIDE 2049   // >=1801, and 2049 % 32 == 1 -> replicas bank-rotated
#define NREP 4
#define THREADS  512
#define BLOCKS   592   // 148 SMs * 4 resident blocks -> single wave

__global__ void zero_out_kernel(float* __restrict__ out, int n) {
    int i = blockIdx.x * blockDim.x + threadIdx.x;
    if (i < n) out[i] = 0.0f;
}

__device__ __forceinline__ void process_one(
    float xv, float yv, float val,
    float Aq, float Bq, float Cq,
    float Ar, float Br, float Cr,
    int R, int rep_off, float* __restrict__ sh)
{
    float q = fmaf(Aq, xv, fmaf(Bq, yv, Cq));
    float r = fmaf(Ar, xv, fmaf(Br, yv, Cr));
    // axial round (round-half-even == jnp.round)
    float s  = -q - r;
    float qr = rintf(q);
    float rr = rintf(r);
    float sr = rintf(s);
    float qd = fabsf(qr - q);
    float rd = fabsf(rr - r);
    float sd = fabsf(sr - s);
    if (qd > rd && qd > sd) qr = -rr - sr;
    if (rd > qd && rd > sd) rr = -qr - sr;   // uses updated qr, like reference

    int a = (int)qr;           // axial q
    int b = (int)rr;           // axial r
    // hex membership + analytic pixel index (q-major enumeration, r ascending)
    int amin = min(a, 0);
    int amax = max(a, 0);
    int rlo  = -R - amin;      // max(-R, -a-R)
    int rhi  =  R - amax;      // min(R, -a+R)
    bool valid = (a >= -R) & (a <= R) & (b >= rlo) & (b <= rhi);
    if (valid) {
        int u = amin + R;
        int e = amax;
        int off = u * (R + 1) + ((u * (u - 1)) >> 1)
                + e * (2 * R + 1) - ((e * (e - 1)) >> 1);
        int pix = off + (b - rlo);
        atomicAdd(&sh[rep_off + pix], val);
    }
}

__global__ __launch_bounds__(THREADS, 4)
void hex_hist_kernel(
    const float* __restrict__ x,
    const float* __restrict__ y,
    const float* __restrict__ vals,
    const float* __restrict__ hs_p,
    const float* __restrict__ rot_p,
    const float* __restrict__ ox_p,
    const float* __restrict__ oy_p,
    const int*   __restrict__ qmin_p,
    float* __restrict__ out,
    int n, int n_pix)
{
    __shared__ float sh[NREP * NPIX_STRIDE];
    for (int i = threadIdx.x; i < NREP * NPIX_STRIDE; i += THREADS) sh[i] = 0.0f;
    __syncthreads();

    // fold rotation + offsets + hex scale into 2 affine maps:
    //   q = Aq*x + Bq*y + Cq     r = Ar*x + Br*y + Cr
    const float hs  = *hs_p;
    const float rot = *rot_p;
    const float ca  = cosf(-rot);
    const float sa  = sinf(-rot);
    const float ox  = *ox_p;
    const float oy  = *oy_p;
    const int   R   = -(*qmin_p);

    const float inv_hs = 1.0f / hs;
    const float c1 = 0.57735026918962576f;  // sqrt(3)/3
    const float c2 = 1.0f / 3.0f;
    const float c3 = 2.0f / 3.0f;
    const float Aq = inv_hs * (c1 * ca - c2 * sa);
    const float Bq = inv_hs * (-c1 * sa - c2 * ca);
    const float Cq = -(Aq * ox + Bq * oy);
    const float Ar = inv_hs * c3 * sa;
    const float Br = inv_hs * c3 * ca;
    const float Cr = -(Ar * ox + Br * oy);

    // replica by lane&3: splits each warp's atomic across 4 bank-rotated copies
    const int rep_off = (threadIdx.x & 3) * NPIX_STRIDE;

    int tid    = blockIdx.x * THREADS + threadIdx.x;
    int stride = gridDim.x * THREADS;

    int n4 = n >> 2;
    const float4* __restrict__ x4 = (const float4*)x;
    const float4* __restrict__ y4 = (const float4*)y;
    const float4* __restrict__ v4 = (const float4*)vals;
    for (int i = tid; i < n4; i += stride) {
        float4 xa = x4[i];
        float4 ya = y4[i];
        float4 va = v4[i];
        process_one(xa.x, ya.x, va.x, Aq, Bq, Cq, Ar, Br, Cr, R, rep_off, sh);
        process_one(xa.y, ya.y, va.y, Aq, Bq, Cq, Ar, Br, Cr, R, rep_off, sh);
        process_one(xa.z, ya.z, va.z, Aq, Bq, Cq, Ar, Br, Cr, R, rep_off, sh);
        process_one(xa.w, ya.w, va.w, Aq, Bq, Cq, Ar, Br, Cr, R, rep_off, sh);
    }
    // tail (n not multiple of 4)
    for (int i = (n4 << 2) + tid; i < n; i += stride) {
        process_one(x[i], y[i], vals[i], Aq, Bq, Cq, Ar, Br, Cr, R, rep_off, sh);
    }

    __syncthreads();
    for (int i = threadIdx.x; i < n_pix; i += THREADS) {
        float v = sh[i]
                + sh[i + NPIX_STRIDE]
                + sh[i + 2 * NPIX_STRIDE]
                + sh[i + 3 * NPIX_STRIDE];
        if (v != 0.0f) atomicAdd(&out[i], v);
    }
}

extern "C" void kernel_launch(void* const* d_in, const int* in_sizes, int n_in,
                              void* d_out, int out_size) {
    const float* x      = (const float*)d_in[0];
    const float* y      = (const float*)d_in[1];
    const float* vals   = (const float*)d_in[2];
    const float* hs_p   = (const float*)d_in[4];
    const float* rot_p  = (const float*)d_in[5];
    const float* ox_p   = (const float*)d_in[6];
    const float* oy_p   = (const float*)d_in[7];
    const int*   qmin_p = (const int*)d_in[8];
    float* out = (float*)d_out;

    int n = in_sizes[0];
    int n_pix = out_size;

    zero_out_kernel<<<(out_size + 255) / 256, 256>>>(out, out_size);

    hex_hist_kernel<<<BLOCKS, THREADS>>>(
        x, y, vals, hs_p, rot_p, ox_p, oy_p, qmin_p,
        out, n, n_pix);
}